// round 2
// baseline (speedup 1.0000x reference)
#include <cuda_runtime.h>
#include <cstdint>

#define BATCH   8192
#define IN_DIM  256
#define HID_DIM 16384
#define OUT_DIM 256
#define K_SEL   256
#define LIST_CAP 512

typedef unsigned long long u64;

// Packed fp32x2 FMA: lane-wise IEEE RN fp32 — bitwise identical to two fmaf().
__device__ __forceinline__ void ffma2(u64& d, u64 a, u64 b) {
    asm("fma.rn.f32x2 %0, %1, %2, %0;" : "+l"(d) : "l"(a), "l"(b));
}
__device__ __forceinline__ u64 pack2(float x, float y) {
    u64 r; asm("mov.b64 %0, {%1, %2};" : "=l"(r) : "f"(x), "f"(y)); return r;
}
__device__ __forceinline__ float2 unpack2(u64 v) {
    float2 f; asm("mov.b64 {%0, %1}, %2;" : "=f"(f.x), "=f"(f.y) : "l"(v)); return f;
}

// Scratch: dec_w transposed to [HID_DIM][OUT_DIM] so a hidden unit's output
// weights are contiguous (1 KB, coalesced) during the sparse decode GEMM.
__device__ float g_dec_wT[(size_t)HID_DIM * OUT_DIM];

// ---------------------------------------------------------------------------
// Kernel 1: transpose dec_w [OUT_DIM][HID_DIM] -> g_dec_wT [HID_DIM][OUT_DIM]
// ---------------------------------------------------------------------------
__global__ void transpose_dec(const float* __restrict__ dec_w)
{
    __shared__ float tile[32][33];
    const int j0 = blockIdx.x * 32;   // hid index
    const int o0 = blockIdx.y * 32;   // out index
    const int tx = threadIdx.x;       // 0..31
    const int ty = threadIdx.y;       // 0..7
#pragma unroll
    for (int i = 0; i < 4; i++) {
        tile[ty + i * 8][tx] = dec_w[(size_t)(o0 + ty + i * 8) * HID_DIM + (j0 + tx)];
    }
    __syncthreads();
#pragma unroll
    for (int i = 0; i < 4; i++) {
        g_dec_wT[(size_t)(j0 + ty + i * 8) * OUT_DIM + (o0 + tx)] = tile[tx][ty + i * 8];
    }
}

// ---------------------------------------------------------------------------
// Kernel 2: h_relu = relu(x @ enc_w^T + enc_b)   [BATCH][HID_DIM]
// fp32 tiled GEMM with packed fma.rn.f32x2 inner product (2x FFMA throughput,
// bitwise-identical rounding to scalar fmaf). BM=BN=128, BK=16, 256 threads,
// 8x8 per thread, double-buffered SMEM.
// ---------------------------------------------------------------------------
__global__ __launch_bounds__(256, 2)
void gemm1_relu(const float* __restrict__ x,
                const float* __restrict__ w,
                const float* __restrict__ bias,
                float* __restrict__ h)
{
    __shared__ float As[2][16][128];   // [k][m]
    __shared__ float Bs[2][16][128];   // [k][n]

    const int tid = threadIdx.x;
    const int m0 = blockIdx.y * 128;
    const int n0 = blockIdx.x * 128;

    const int ty = tid >> 4;          // 0..15 (row group)
    const int tx = tid & 15;          // 0..15 (col group)

    // acc2[i][j] holds columns (2j, 2j+1) for row i, packed fp32x2.
    u64 acc2[8][4];
#pragma unroll
    for (int i = 0; i < 8; i++)
#pragma unroll
        for (int j = 0; j < 4; j++) acc2[i][j] = 0ull;

    // Load mapping: 512 float4 per operand per stage, 2 per thread.
    const int r0 = (tid + 0)   >> 2, kq0 = (tid + 0)   & 3;
    const int r1 = (tid + 256) >> 2, kq1 = (tid + 256) & 3;

    float4 xa0, xa1, wa0, wa1;

    // prologue: stage 0
    {
        const int k0 = 0;
        xa0 = *(const float4*)&x[(size_t)(m0 + r0) * IN_DIM + k0 + kq0 * 4];
        xa1 = *(const float4*)&x[(size_t)(m0 + r1) * IN_DIM + k0 + kq1 * 4];
        wa0 = *(const float4*)&w[(size_t)(n0 + r0) * IN_DIM + k0 + kq0 * 4];
        wa1 = *(const float4*)&w[(size_t)(n0 + r1) * IN_DIM + k0 + kq1 * 4];
        As[0][kq0 * 4 + 0][r0] = xa0.x; As[0][kq0 * 4 + 1][r0] = xa0.y;
        As[0][kq0 * 4 + 2][r0] = xa0.z; As[0][kq0 * 4 + 3][r0] = xa0.w;
        As[0][kq1 * 4 + 0][r1] = xa1.x; As[0][kq1 * 4 + 1][r1] = xa1.y;
        As[0][kq1 * 4 + 2][r1] = xa1.z; As[0][kq1 * 4 + 3][r1] = xa1.w;
        Bs[0][kq0 * 4 + 0][r0] = wa0.x; Bs[0][kq0 * 4 + 1][r0] = wa0.y;
        Bs[0][kq0 * 4 + 2][r0] = wa0.z; Bs[0][kq0 * 4 + 3][r0] = wa0.w;
        Bs[0][kq1 * 4 + 0][r1] = wa1.x; Bs[0][kq1 * 4 + 1][r1] = wa1.y;
        Bs[0][kq1 * 4 + 2][r1] = wa1.z; Bs[0][kq1 * 4 + 3][r1] = wa1.w;
    }
    __syncthreads();

    const int NSTAGE = IN_DIM / 16;   // 16
    for (int s = 0; s < NSTAGE; s++) {
        const int cur = s & 1;
        const int nxt = cur ^ 1;
        if (s + 1 < NSTAGE) {
            const int k0 = (s + 1) * 16;
            xa0 = *(const float4*)&x[(size_t)(m0 + r0) * IN_DIM + k0 + kq0 * 4];
            xa1 = *(const float4*)&x[(size_t)(m0 + r1) * IN_DIM + k0 + kq1 * 4];
            wa0 = *(const float4*)&w[(size_t)(n0 + r0) * IN_DIM + k0 + kq0 * 4];
            wa1 = *(const float4*)&w[(size_t)(n0 + r1) * IN_DIM + k0 + kq1 * 4];
        }

#pragma unroll
        for (int kk = 0; kk < 16; kk++) {
            float a[8];
            *(float4*)&a[0] = *(const float4*)&As[cur][kk][ty * 8 + 0];
            *(float4*)&a[4] = *(const float4*)&As[cur][kk][ty * 8 + 4];
            const float4 bA = *(const float4*)&Bs[cur][kk][tx * 8 + 0];
            const float4 bB = *(const float4*)&Bs[cur][kk][tx * 8 + 4];
            const u64 b20 = pack2(bA.x, bA.y);
            const u64 b21 = pack2(bA.z, bA.w);
            const u64 b22 = pack2(bB.x, bB.y);
            const u64 b23 = pack2(bB.z, bB.w);
#pragma unroll
            for (int i = 0; i < 8; i++) {
                const u64 a2 = pack2(a[i], a[i]);
                ffma2(acc2[i][0], a2, b20);
                ffma2(acc2[i][1], a2, b21);
                ffma2(acc2[i][2], a2, b22);
                ffma2(acc2[i][3], a2, b23);
            }
        }

        if (s + 1 < NSTAGE) {
            As[nxt][kq0 * 4 + 0][r0] = xa0.x; As[nxt][kq0 * 4 + 1][r0] = xa0.y;
            As[nxt][kq0 * 4 + 2][r0] = xa0.z; As[nxt][kq0 * 4 + 3][r0] = xa0.w;
            As[nxt][kq1 * 4 + 0][r1] = xa1.x; As[nxt][kq1 * 4 + 1][r1] = xa1.y;
            As[nxt][kq1 * 4 + 2][r1] = xa1.z; As[nxt][kq1 * 4 + 3][r1] = xa1.w;
            Bs[nxt][kq0 * 4 + 0][r0] = wa0.x; Bs[nxt][kq0 * 4 + 1][r0] = wa0.y;
            Bs[nxt][kq0 * 4 + 2][r0] = wa0.z; Bs[nxt][kq0 * 4 + 3][r0] = wa0.w;
            Bs[nxt][kq1 * 4 + 0][r1] = wa1.x; Bs[nxt][kq1 * 4 + 1][r1] = wa1.y;
            Bs[nxt][kq1 * 4 + 2][r1] = wa1.z; Bs[nxt][kq1 * 4 + 3][r1] = wa1.w;
        }
        __syncthreads();
    }

    // epilogue: bias + relu, write h
    float bv[8];
    *(float4*)&bv[0] = *(const float4*)&bias[n0 + tx * 8 + 0];
    *(float4*)&bv[4] = *(const float4*)&bias[n0 + tx * 8 + 4];

#pragma unroll
    for (int i = 0; i < 8; i++) {
        const size_t grow = (size_t)(m0 + ty * 8 + i) * HID_DIM + n0 + tx * 8;
        float4 v0, v1;
        float t;
        float2 p;
        p = unpack2(acc2[i][0]);
        t = p.x + bv[0]; v0.x = t > 0.0f ? t : 0.0f;
        t = p.y + bv[1]; v0.y = t > 0.0f ? t : 0.0f;
        p = unpack2(acc2[i][1]);
        t = p.x + bv[2]; v0.z = t > 0.0f ? t : 0.0f;
        t = p.y + bv[3]; v0.w = t > 0.0f ? t : 0.0f;
        p = unpack2(acc2[i][2]);
        t = p.x + bv[4]; v1.x = t > 0.0f ? t : 0.0f;
        t = p.y + bv[5]; v1.y = t > 0.0f ? t : 0.0f;
        p = unpack2(acc2[i][3]);
        t = p.x + bv[6]; v1.z = t > 0.0f ? t : 0.0f;
        t = p.y + bv[7]; v1.w = t > 0.0f ? t : 0.0f;
        *(float4*)&h[grow + 0] = v0;
        *(float4*)&h[grow + 4] = v1;
    }
}

// ---------------------------------------------------------------------------
// Kernel 3: per-row exact top-K threshold (32-bit radix select), apply
// threshold (write hidden_post), sparse decode GEMM (+dec_b) -> output row.
// One CTA (256 threads) per batch row. Row staged in dynamic SMEM (64 KB).
// ---------------------------------------------------------------------------
__global__ void topk_apply_gemm2(const float* __restrict__ dec_b,
                                 float* __restrict__ out,      // [BATCH][OUT_DIM]
                                 float* __restrict__ hidden)   // [BATCH][HID_DIM]
{
    extern __shared__ float row[];            // HID_DIM floats
    __shared__ unsigned hist[256];
    __shared__ unsigned s_prefix;
    __shared__ int s_r;
    __shared__ int scan[256];
    __shared__ int list_j[LIST_CAP];
    __shared__ float list_v[LIST_CAP];
    __shared__ int s_total;

    const int tid = threadIdx.x;
    const int brow = blockIdx.x;
    float* hrow = hidden + (size_t)brow * HID_DIM;

    // stage row into smem (coalesced float4)
    {
        const float4* src = (const float4*)hrow;
        float4* dst = (float4*)row;
        for (int i = tid; i < HID_DIM / 4; i += 256) dst[i] = src[i];
    }
    if (tid == 0) { s_prefix = 0u; s_r = K_SEL; }
    __syncthreads();

    // ---- 4-pass radix select (MSB first) for K-th largest exact key ----
    for (int shift = 24; shift >= 0; shift -= 8) {
        hist[tid] = 0u;
        __syncthreads();
        const unsigned prefix = s_prefix;
        const unsigned himask = (shift == 24) ? 0u : (0xFFFFFFFFu << (shift + 8));
        for (int i = tid; i < HID_DIM; i += 256) {
            const unsigned u = __float_as_uint(row[i]);
            const bool cand = ((u & himask) == (prefix & himask));
            const unsigned d = (u >> shift) & 255u;
            const unsigned active = __ballot_sync(0xffffffffu, cand);
            if (cand) {
                const unsigned peers = __match_any_sync(active, d);
                const int leader = __ffs(peers) - 1;
                if ((int)(threadIdx.x & 31) == leader)
                    atomicAdd(&hist[d], (unsigned)__popc(peers));
            }
        }
        __syncthreads();
        if (tid == 0) {
            int r = s_r;
            unsigned acc = 0;
            int d = 255;
            for (; d > 0; --d) {
                const unsigned c = hist[d];
                if (acc + c >= (unsigned)r) break;
                acc += c;
            }
            s_prefix = prefix | ((unsigned)d << shift);
            s_r = r - (int)acc;
        }
        __syncthreads();
    }
    const float t = __uint_as_float(s_prefix);
    const bool dense_path = !(t > 0.0f);   // threshold 0 keeps everything

    // ---- deterministic compaction of kept (j, v) pairs ----
    int cnt = 0;
    if (!dense_path) {
        for (int i = tid; i < HID_DIM; i += 256)
            if (row[i] >= t) cnt++;
    }
    scan[tid] = cnt;
    __syncthreads();
#pragma unroll
    for (int off = 1; off < 256; off <<= 1) {
        const int add = (tid >= off) ? scan[tid - off] : 0;
        __syncthreads();
        scan[tid] += add;
        __syncthreads();
    }
    if (tid == 255) s_total = scan[255];
    int base = scan[tid] - cnt;
    __syncthreads();

    if (!dense_path) {
        for (int i = tid; i < HID_DIM; i += 256) {
            const float v = row[i];
            if (v >= t) {
                if (base < LIST_CAP) { list_j[base] = i; list_v[base] = v; }
                base++;
            } else {
                row[i] = 0.0f;
            }
        }
    }
    __syncthreads();

    // ---- write hidden_post back (row now holds post-threshold values) ----
    {
        const float4* src = (const float4*)row;
        float4* dst = (float4*)hrow;
        for (int i = tid; i < HID_DIM / 4; i += 256) dst[i] = src[i];
    }

    // ---- sparse decode GEMM: out[brow][tid] = dec_b[tid] + sum v * dec_wT[j][tid]
    float acc = dec_b[tid];
    if (!dense_path) {
        const int nsel = (s_total < LIST_CAP) ? s_total : LIST_CAP;
        int s = 0;
        for (; s + 4 <= nsel; s += 4) {
            acc = fmaf(list_v[s + 0], g_dec_wT[(size_t)list_j[s + 0] * OUT_DIM + tid], acc);
            acc = fmaf(list_v[s + 1], g_dec_wT[(size_t)list_j[s + 1] * OUT_DIM + tid], acc);
            acc = fmaf(list_v[s + 2], g_dec_wT[(size_t)list_j[s + 2] * OUT_DIM + tid], acc);
            acc = fmaf(list_v[s + 3], g_dec_wT[(size_t)list_j[s + 3] * OUT_DIM + tid], acc);
        }
        for (; s < nsel; s++)
            acc = fmaf(list_v[s], g_dec_wT[(size_t)list_j[s] * OUT_DIM + tid], acc);
    } else {
        for (int j = 0; j < HID_DIM; j++)
            acc = fmaf(row[j], g_dec_wT[(size_t)j * OUT_DIM + tid], acc);
    }
    out[(size_t)brow * OUT_DIM + tid] = acc;
}

// ---------------------------------------------------------------------------
// Launch
// ---------------------------------------------------------------------------
extern "C" void kernel_launch(void* const* d_in, const int* in_sizes, int n_in,
                              void* d_out, int out_size)
{
    const float* x     = (const float*)d_in[0];   // [BATCH][IN_DIM]
    const float* enc_w = (const float*)d_in[1];   // [HID_DIM][IN_DIM]
    const float* enc_b = (const float*)d_in[2];   // [HID_DIM]
    const float* dec_w = (const float*)d_in[3];   // [OUT_DIM][HID_DIM]
    const float* dec_b = (const float*)d_in[4];   // [OUT_DIM]
    // d_in[5] = k (always 256 for this problem)

    float* out    = (float*)d_out;                          // [BATCH][OUT_DIM]
    float* hidden = (float*)d_out + (size_t)BATCH * OUT_DIM; // [BATCH][HID_DIM]

    cudaFuncSetAttribute(topk_apply_gemm2,
                         cudaFuncAttributeMaxDynamicSharedMemorySize,
                         HID_DIM * sizeof(float));

    // 1) transpose dec_w
    {
        dim3 grid(HID_DIM / 32, OUT_DIM / 32);
        dim3 block(32, 8);
        transpose_dec<<<grid, block>>>(dec_w);
    }
    // 2) encoder GEMM + relu -> hidden region of d_out
    {
        dim3 grid(HID_DIM / 128, BATCH / 128);
        gemm1_relu<<<grid, 256>>>(x, enc_w, enc_b, hidden);
    }
    // 3) per-row top-k threshold + apply + sparse decode
    {
        topk_apply_gemm2<<<BATCH, 256, HID_DIM * sizeof(float)>>>(dec_b, out, hidden);
    }
}

// round 5
// speedup vs baseline: 1.3093x; 1.3093x over previous
#include <cuda_runtime.h>
#include <cuda_bf16.h>
#include <cstdint>

#define BATCH   8192
#define IN_DIM  256
#define HID_DIM 16384
#define OUT_DIM 256
#define K_SEL   256
#define LIST_CAP 512
#define BAND_CAP 64

// bf16x2 split GEMM (3 terms): K expanded 3x (hi*hi, hi*mid, mid*hi)
#define KTOT  768

// HMMA tile config
#define BM 128
#define BN 128
#define BK 32
#define NSTAGES 4
#define KITERS (KTOT / BK)          // 24
#define STAGE_BYTES (2 * BM * BK * 2)   // A half + B half = 16384
#define GEMM_SMEM (NSTAGES * STAGE_BYTES) // 65536

typedef unsigned long long u64;

// ---------------------------------------------------------------------------
// Device scratch
// ---------------------------------------------------------------------------
__device__ float         g_dec_wT[(size_t)HID_DIM * OUT_DIM];
__device__ __nv_bfloat16 g_xs[(size_t)BATCH  * KTOT];
__device__ __nv_bfloat16 g_ws[(size_t)HID_DIM * KTOT];

// ---------------------------------------------------------------------------
// PTX helpers (sm_80-level: cp.async / ldmatrix / mma.sync — no 'a' features)
// ---------------------------------------------------------------------------
__device__ __forceinline__ uint32_t smem_u32(const void* p) {
    uint32_t a;
    asm("{ .reg .u64 t; cvta.to.shared.u64 t, %1; cvt.u32.u64 %0, t; }" : "=r"(a) : "l"(p));
    return a;
}
__device__ __forceinline__ void cp16(uint32_t dst, const void* src) {
    asm volatile("cp.async.cg.shared.global [%0], [%1], 16;" :: "r"(dst), "l"(src));
}
__device__ __forceinline__ void cp_commit() {
    asm volatile("cp.async.commit_group;" ::: "memory");
}
__device__ __forceinline__ void ldsm4(uint32_t& r0, uint32_t& r1, uint32_t& r2, uint32_t& r3,
                                      uint32_t addr) {
    asm volatile("ldmatrix.sync.aligned.m8n8.x4.shared.b16 {%0,%1,%2,%3}, [%4];"
                 : "=r"(r0), "=r"(r1), "=r"(r2), "=r"(r3) : "r"(addr));
}
__device__ __forceinline__ void mma16816(float* c, const uint32_t* a, const uint32_t* b) {
    asm volatile(
        "mma.sync.aligned.m16n8k16.row.col.f32.bf16.bf16.f32 "
        "{%0,%1,%2,%3}, {%4,%5,%6,%7}, {%8,%9}, {%0,%1,%2,%3};"
        : "+f"(c[0]), "+f"(c[1]), "+f"(c[2]), "+f"(c[3])
        : "r"(a[0]), "r"(a[1]), "r"(a[2]), "r"(a[3]), "r"(b[0]), "r"(b[1]));
}

// ---------------------------------------------------------------------------
// split fp32 -> 2x bf16 along expanded K (3-term product)
// A segs: [hi, hi, mid] ; B segs: [hi, mid, hi]
// ---------------------------------------------------------------------------
__global__ void split_x(const float* __restrict__ x)
{
    const int i = blockIdx.x * 256 + threadIdx.x;
    const int m = i >> 8, k = i & 255;
    const float v = x[i];
    const __nv_bfloat16 hi = __float2bfloat16(v);
    const float r1 = v - __bfloat162float(hi);
    const __nv_bfloat16 mid = __float2bfloat16(r1);
    __nv_bfloat16* dst = g_xs + (size_t)m * KTOT + k;
    dst[0] = hi; dst[256] = hi; dst[512] = mid;
}
__global__ void split_w(const float* __restrict__ w)
{
    const int i = blockIdx.x * 256 + threadIdx.x;
    const int n = i >> 8, k = i & 255;
    const float v = w[i];
    const __nv_bfloat16 hi = __float2bfloat16(v);
    const float r1 = v - __bfloat162float(hi);
    const __nv_bfloat16 mid = __float2bfloat16(r1);
    __nv_bfloat16* dst = g_ws + (size_t)n * KTOT + k;
    dst[0] = hi; dst[256] = mid; dst[512] = hi;
}

// ---------------------------------------------------------------------------
// HMMA bf16 GEMM:  h = relu(A' B'^T + bias)
// ---------------------------------------------------------------------------
__device__ __forceinline__ uint32_t sw_off(int row, int gran) {
    return (uint32_t)(row * 64 + ((gran ^ ((row >> 1) & 3)) << 4));
}

__global__ __launch_bounds__(256, 2)
void gemm1_mma(const float* __restrict__ bias, float* __restrict__ h)
{
    extern __shared__ __align__(1024) char smem[];
    const uint32_t sb = smem_u32(smem);
    const int tid = threadIdx.x;
    const int wid = tid >> 5;
    const int lane = tid & 31;
    const int m0 = blockIdx.x * BM;
    const int n0 = blockIdx.y * BN;

    const int warp_m = wid >> 2;
    const int warp_n = wid & 3;

    float acc[4][4][4];
#pragma unroll
    for (int i = 0; i < 4; i++)
#pragma unroll
        for (int j = 0; j < 4; j++)
#pragma unroll
            for (int q = 0; q < 4; q++) acc[i][j][q] = 0.0f;

    const int ar0 = (tid + 0)   >> 2, ag0 = (tid + 0)   & 3;
    const int ar1 = (tid + 256) >> 2, ag1 = (tid + 256) & 3;

    auto issue = [&](int c, int s) {
        const uint32_t abase = sb + s * STAGE_BYTES;
        const uint32_t bbase = abase + BM * BK * 2;
        const __nv_bfloat16* ax = g_xs + (size_t)m0 * KTOT + c * BK;
        const __nv_bfloat16* bx = g_ws + (size_t)n0 * KTOT + c * BK;
        cp16(abase + sw_off(ar0, ag0), ax + (size_t)ar0 * KTOT + ag0 * 8);
        cp16(abase + sw_off(ar1, ag1), ax + (size_t)ar1 * KTOT + ag1 * 8);
        cp16(bbase + sw_off(ar0, ag0), bx + (size_t)ar0 * KTOT + ag0 * 8);
        cp16(bbase + sw_off(ar1, ag1), bx + (size_t)ar1 * KTOT + ag1 * 8);
    };

    issue(0, 0); cp_commit();
    issue(1, 1); cp_commit();
    issue(2, 2); cp_commit();

    const int a_row_in = warp_m * 64 + (lane & 15);
    const int a_gsel   = (lane >> 4);
    const int b_row_in = warp_n * 32 + (lane & 7) + ((lane >> 4) << 3);
    const int b_gsel   = (lane >> 3) & 1;

    for (int c = 0; c < KITERS; c++) {
        asm volatile("cp.async.wait_group 2;" ::: "memory");
        __syncthreads();

        if (c + 3 < KITERS) issue(c + 3, (c + 3) & (NSTAGES - 1));
        cp_commit();

        const uint32_t abase = sb + (c & (NSTAGES - 1)) * STAGE_BYTES;
        const uint32_t bbase = abase + BM * BK * 2;

#pragma unroll
        for (int ks = 0; ks < 2; ks++) {
            uint32_t af[4][4];
            uint32_t bf[4][2];
#pragma unroll
            for (int ti = 0; ti < 4; ti++) {
                const int r = a_row_in + ti * 16;
                ldsm4(af[ti][0], af[ti][1], af[ti][2], af[ti][3],
                      abase + sw_off(r, ks * 2 + a_gsel));
            }
#pragma unroll
            for (int tjj = 0; tjj < 2; tjj++) {
                const int r = b_row_in + tjj * 16;
                uint32_t r0, r1, r2, r3;
                ldsm4(r0, r1, r2, r3, bbase + sw_off(r, ks * 2 + b_gsel));
                bf[tjj * 2 + 0][0] = r0; bf[tjj * 2 + 0][1] = r1;
                bf[tjj * 2 + 1][0] = r2; bf[tjj * 2 + 1][1] = r3;
            }
#pragma unroll
            for (int ti = 0; ti < 4; ti++)
#pragma unroll
                for (int tj = 0; tj < 4; tj++)
                    mma16816(acc[ti][tj], af[ti], bf[tj]);
        }
        __syncthreads();
    }

    // epilogue: SMEM bounce for coalesced stores
    __syncthreads();
    float* esm = (float*)smem + wid * (64 * 32);
#pragma unroll
    for (int ti = 0; ti < 4; ti++)
#pragma unroll
        for (int tj = 0; tj < 4; tj++) {
            const int r = ti * 16 + (lane >> 2);
            const int cc = tj * 8 + (lane & 3) * 2;
            esm[r * 32 + cc]            = acc[ti][tj][0];
            esm[r * 32 + cc + 1]        = acc[ti][tj][1];
            esm[(r + 8) * 32 + cc]      = acc[ti][tj][2];
            esm[(r + 8) * 32 + cc + 1]  = acc[ti][tj][3];
        }
    __syncwarp();
    {
        const int col = n0 + warp_n * 32 + lane;
        const float bl = bias[col];
        float* hb = h + (size_t)(m0 + warp_m * 64) * HID_DIM + col;
#pragma unroll 4
        for (int r = 0; r < 64; r++) {
            float v = esm[r * 32 + lane] + bl;
            hb[(size_t)r * HID_DIM] = v > 0.0f ? v : 0.0f;
        }
    }
}

// ---------------------------------------------------------------------------
// transpose dec_w
// ---------------------------------------------------------------------------
__global__ void transpose_dec(const float* __restrict__ dec_w)
{
    __shared__ float tile[32][33];
    const int j0 = blockIdx.x * 32;
    const int o0 = blockIdx.y * 32;
    const int tx = threadIdx.x;
    const int ty = threadIdx.y;
#pragma unroll
    for (int i = 0; i < 4; i++)
        tile[ty + i * 8][tx] = dec_w[(size_t)(o0 + ty + i * 8) * HID_DIM + (j0 + tx)];
    __syncthreads();
#pragma unroll
    for (int i = 0; i < 4; i++)
        g_dec_wT[(size_t)(j0 + ty + i * 8) * OUT_DIM + (o0 + tx)] = tile[tx][ty + i * 8];
}

// ---------------------------------------------------------------------------
// per-row top-K with exact-fp32 boundary band + threshold + sparse decode
// ---------------------------------------------------------------------------
__global__ void topk_apply_gemm2(const float* __restrict__ x,
                                 const float* __restrict__ enc_w,
                                 const float* __restrict__ enc_b,
                                 const float* __restrict__ dec_b,
                                 float* __restrict__ out,
                                 float* __restrict__ hidden)
{
    extern __shared__ float row[];            // HID_DIM floats (approx h)
    __shared__ unsigned hist[256];
    __shared__ unsigned s_prefix;
    __shared__ int s_r;
    __shared__ int scan[256];
    __shared__ int list_j[LIST_CAP];
    __shared__ float list_v[LIST_CAP];
    __shared__ int s_total;
    __shared__ unsigned bitmap[HID_DIM / 32];  // 512 words
    __shared__ float xrow[IN_DIM];
    __shared__ int band_idx[BAND_CAP];
    __shared__ float band_ex[BAND_CAP];
    __shared__ int s_bandcnt, s_chi;

    const int tid = threadIdx.x;
    const int lane = tid & 31;
    const int warp = tid >> 5;
    const int brow = blockIdx.x;
    float* hrow = hidden + (size_t)brow * HID_DIM;

    {
        const float4* src = (const float4*)hrow;
        float4* dst = (float4*)row;
        for (int i = tid; i < HID_DIM / 4; i += 256) dst[i] = src[i];
    }
    if (tid == 0) { s_prefix = 0u; s_r = K_SEL; s_bandcnt = 0; s_chi = 0; }
    xrow[tid] = x[(size_t)brow * IN_DIM + tid];
    __syncthreads();

    // ---- radix select on approx values ----
    for (int shift = 24; shift >= 0; shift -= 8) {
        hist[tid] = 0u;
        __syncthreads();
        const unsigned prefix = s_prefix;
        const unsigned himask = (shift == 24) ? 0u : (0xFFFFFFFFu << (shift + 8));
        for (int i = tid; i < HID_DIM; i += 256) {
            const unsigned u = __float_as_uint(row[i]);
            const bool cand = ((u & himask) == (prefix & himask));
            const unsigned d = (u >> shift) & 255u;
            const unsigned active = __ballot_sync(0xffffffffu, cand);
            if (cand) {
                const unsigned peers = __match_any_sync(active, d);
                const int leader = __ffs(peers) - 1;
                if (lane == leader) atomicAdd(&hist[d], (unsigned)__popc(peers));
            }
        }
        __syncthreads();
        if (tid == 0) {
            int r = s_r;
            unsigned acc = 0;
            int d = 255;
            for (; d > 0; --d) {
                const unsigned c = hist[d];
                if (acc + c >= (unsigned)r) break;
                acc += c;
            }
            s_prefix = prefix | ((unsigned)d << shift);
            s_r = r - (int)acc;
        }
        __syncthreads();
    }
    const float t = __uint_as_float(s_prefix);
    const float eps = 3e-3f;
    const bool band_path = (t > eps);
    const bool dense_path = !(t > 0.0f);

    if (band_path) {
        // B1: bitmap of definite-ins (> t+eps), count them, collect band
        int my_hi = 0;
        for (int w = warp; w < HID_DIM / 32; w += 8) {
            const int i = w * 32 + lane;
            const float v = row[i];
            const bool hi_keep = v > t + eps;
            const unsigned bits = __ballot_sync(0xffffffffu, hi_keep);
            if (lane == 0) bitmap[w] = bits;
            my_hi += hi_keep;
            const bool inband = (!hi_keep) && (v >= t - eps);
            if (inband) {
                const int p = atomicAdd(&s_bandcnt, 1);
                if (p < BAND_CAP) band_idx[p] = i;
            }
        }
        atomicAdd(&s_chi, my_hi);
        __syncthreads();
        const int bc = (s_bandcnt < BAND_CAP) ? s_bandcnt : BAND_CAP;
        const int k_rem = K_SEL - s_chi;
        // exact recompute (sequential-k fp32, matches proven-safe ordering)
        if (tid < bc) {
            const int j = band_idx[tid];
            const float4* wj = (const float4*)(enc_w + (size_t)j * IN_DIM);
            float acc = 0.0f;
#pragma unroll 8
            for (int k4 = 0; k4 < IN_DIM / 4; k4++) {
                const float4 wv = __ldg(&wj[k4]);
                acc = fmaf(xrow[k4 * 4 + 0], wv.x, acc);
                acc = fmaf(xrow[k4 * 4 + 1], wv.y, acc);
                acc = fmaf(xrow[k4 * 4 + 2], wv.z, acc);
                acc = fmaf(xrow[k4 * 4 + 3], wv.w, acc);
            }
            acc += enc_b[j];
            band_ex[tid] = acc > 0.0f ? acc : 0.0f;
        }
        __syncthreads();
        // rank within band by exact values; keep top k_rem (ties kept, >= semantics)
        if (tid < bc) {
            const float mine = band_ex[tid];
            int gt = 0;
            for (int j2 = 0; j2 < bc; j2++) gt += (band_ex[j2] > mine);
            const int i = band_idx[tid];
            if (gt < k_rem) {
                row[i] = band_ex[tid];       // exact value for kept boundary elt
                atomicOr(&bitmap[i >> 5], 1u << (i & 31));
            }
        }
        __syncthreads();
    }

    // ---- deterministic compaction ----
    int cnt = 0;
    if (band_path) {
        for (int i = tid; i < HID_DIM; i += 256)
            cnt += (int)((bitmap[i >> 5] >> (i & 31)) & 1u);
    } else if (!dense_path) {
        for (int i = tid; i < HID_DIM; i += 256)
            if (row[i] >= t) cnt++;
    }
    scan[tid] = cnt;
    __syncthreads();
#pragma unroll
    for (int off = 1; off < 256; off <<= 1) {
        const int add = (tid >= off) ? scan[tid - off] : 0;
        __syncthreads();
        scan[tid] += add;
        __syncthreads();
    }
    if (tid == 255) s_total = scan[255];
    int base = scan[tid] - cnt;
    __syncthreads();

    if (band_path) {
        for (int i = tid; i < HID_DIM; i += 256) {
            const unsigned bit = (bitmap[i >> 5] >> (i & 31)) & 1u;
            if (bit) {
                if (base < LIST_CAP) { list_j[base] = i; list_v[base] = row[i]; }
                base++;
            } else {
                row[i] = 0.0f;
            }
        }
    } else if (!dense_path) {
        for (int i = tid; i < HID_DIM; i += 256) {
            const float v = row[i];
            if (v >= t) {
                if (base < LIST_CAP) { list_j[base] = i; list_v[base] = v; }
                base++;
            } else {
                row[i] = 0.0f;
            }
        }
    }
    __syncthreads();

    // write hidden_post back
    {
        const float4* src = (const float4*)row;
        float4* dst = (float4*)hrow;
        for (int i = tid; i < HID_DIM / 4; i += 256) dst[i] = src[i];
    }

    // sparse decode GEMM
    float acc = dec_b[tid];
    if (!dense_path) {
        const int nsel = (s_total < LIST_CAP) ? s_total : LIST_CAP;
        int s = 0;
        for (; s + 4 <= nsel; s += 4) {
            acc = fmaf(list_v[s + 0], g_dec_wT[(size_t)list_j[s + 0] * OUT_DIM + tid], acc);
            acc = fmaf(list_v[s + 1], g_dec_wT[(size_t)list_j[s + 1] * OUT_DIM + tid], acc);
            acc = fmaf(list_v[s + 2], g_dec_wT[(size_t)list_j[s + 2] * OUT_DIM + tid], acc);
            acc = fmaf(list_v[s + 3], g_dec_wT[(size_t)list_j[s + 3] * OUT_DIM + tid], acc);
        }
        for (; s < nsel; s++)
            acc = fmaf(list_v[s], g_dec_wT[(size_t)list_j[s] * OUT_DIM + tid], acc);
    } else {
        for (int j = 0; j < HID_DIM; j++)
            acc = fmaf(row[j], g_dec_wT[(size_t)j * OUT_DIM + tid], acc);
    }
    out[(size_t)brow * OUT_DIM + tid] = acc;
}

// ---------------------------------------------------------------------------
// Launch
// ---------------------------------------------------------------------------
extern "C" void kernel_launch(void* const* d_in, const int* in_sizes, int n_in,
                              void* d_out, int out_size)
{
    const float* x     = (const float*)d_in[0];
    const float* enc_w = (const float*)d_in[1];
    const float* enc_b = (const float*)d_in[2];
    const float* dec_w = (const float*)d_in[3];
    const float* dec_b = (const float*)d_in[4];

    float* out    = (float*)d_out;
    float* hidden = (float*)d_out + (size_t)BATCH * OUT_DIM;

    cudaFuncSetAttribute(topk_apply_gemm2,
                         cudaFuncAttributeMaxDynamicSharedMemorySize,
                         HID_DIM * sizeof(float));
    cudaFuncSetAttribute(gemm1_mma,
                         cudaFuncAttributeMaxDynamicSharedMemorySize,
                         GEMM_SMEM);

    // 1) transpose dec_w for the sparse decode
    {
        dim3 grid(HID_DIM / 32, OUT_DIM / 32);
        dim3 block(32, 8);
        transpose_dec<<<grid, block>>>(dec_w);
    }
    // 2) bf16 splits of x and enc_w (3-term)
    split_x<<<(BATCH * IN_DIM) / 256, 256>>>(x);
    split_w<<<((size_t)HID_DIM * IN_DIM) / 256, 256>>>(enc_w);

    // 3) tensor-core (HMMA) encoder GEMM + bias + relu
    {
        dim3 grid(BATCH / BM, HID_DIM / BN);
        gemm1_mma<<<grid, 256, GEMM_SMEM>>>(enc_b, hidden);
    }
    // 4) per-row top-k (exact boundary) + apply + sparse decode
    topk_apply_gemm2<<<BATCH, 256, HID_DIM * sizeof(float)>>>(
        x, enc_w, enc_b, dec_b, out, hidden);
}

// round 6
// speedup vs baseline: 1.6295x; 1.2446x over previous
#include <cuda_runtime.h>
#include <cuda_bf16.h>
#include <cstdint>

#define BATCH   8192
#define IN_DIM  256
#define HID_DIM 16384
#define OUT_DIM 256
#define K_SEL   256
#define LIST_CAP 512
#define BAND_CAP 64
#define CAND_CAP 1024
#define NT       512

// bf16x2 split GEMM (3 terms): K expanded 3x (hi*hi, hi*mid, mid*hi)
#define KTOT  768

// HMMA tile config
#define BM 128
#define BN 128
#define BK 32
#define NSTAGES 4
#define KITERS (KTOT / BK)
#define STAGE_BYTES (2 * BM * BK * 2)
#define GEMM_SMEM (NSTAGES * STAGE_BYTES)

typedef unsigned long long u64;

__device__ float         g_dec_wT[(size_t)HID_DIM * OUT_DIM];
__device__ __nv_bfloat16 g_xs[(size_t)BATCH  * KTOT];
__device__ __nv_bfloat16 g_ws[(size_t)HID_DIM * KTOT];

// ---------------------------------------------------------------------------
// PTX helpers (sm_80-level only: no 'a'-gated features; ptxas targets sm_103)
// ---------------------------------------------------------------------------
__device__ __forceinline__ uint32_t smem_u32(const void* p) {
    uint32_t a;
    asm("{ .reg .u64 t; cvta.to.shared.u64 t, %1; cvt.u32.u64 %0, t; }" : "=r"(a) : "l"(p));
    return a;
}
__device__ __forceinline__ void cp16(uint32_t dst, const void* src) {
    asm volatile("cp.async.cg.shared.global [%0], [%1], 16;" :: "r"(dst), "l"(src));
}
__device__ __forceinline__ void cp_commit() {
    asm volatile("cp.async.commit_group;" ::: "memory");
}
__device__ __forceinline__ void ldsm4(uint32_t& r0, uint32_t& r1, uint32_t& r2, uint32_t& r3,
                                      uint32_t addr) {
    asm volatile("ldmatrix.sync.aligned.m8n8.x4.shared.b16 {%0,%1,%2,%3}, [%4];"
                 : "=r"(r0), "=r"(r1), "=r"(r2), "=r"(r3) : "r"(addr));
}
__device__ __forceinline__ void mma16816(float* c, const uint32_t* a, const uint32_t* b) {
    asm volatile(
        "mma.sync.aligned.m16n8k16.row.col.f32.bf16.bf16.f32 "
        "{%0,%1,%2,%3}, {%4,%5,%6,%7}, {%8,%9}, {%0,%1,%2,%3};"
        : "+f"(c[0]), "+f"(c[1]), "+f"(c[2]), "+f"(c[3])
        : "r"(a[0]), "r"(a[1]), "r"(a[2]), "r"(a[3]), "r"(b[0]), "r"(b[1]));
}

// ---------------------------------------------------------------------------
// split fp32 -> 2x bf16 along expanded K (3-term product)
// ---------------------------------------------------------------------------
__global__ void split_x(const float* __restrict__ x)
{
    const int i = blockIdx.x * 256 + threadIdx.x;
    const int m = i >> 8, k = i & 255;
    const float v = x[i];
    const __nv_bfloat16 hi = __float2bfloat16(v);
    const float r1 = v - __bfloat162float(hi);
    const __nv_bfloat16 mid = __float2bfloat16(r1);
    __nv_bfloat16* dst = g_xs + (size_t)m * KTOT + k;
    dst[0] = hi; dst[256] = hi; dst[512] = mid;
}
__global__ void split_w(const float* __restrict__ w)
{
    const int i = blockIdx.x * 256 + threadIdx.x;
    const int n = i >> 8, k = i & 255;
    const float v = w[i];
    const __nv_bfloat16 hi = __float2bfloat16(v);
    const float r1 = v - __bfloat162float(hi);
    const __nv_bfloat16 mid = __float2bfloat16(r1);
    __nv_bfloat16* dst = g_ws + (size_t)n * KTOT + k;
    dst[0] = hi; dst[256] = mid; dst[512] = hi;
}

// ---------------------------------------------------------------------------
// HMMA bf16 GEMM:  h = relu(A' B'^T + bias)   (unchanged from round 5)
// ---------------------------------------------------------------------------
__device__ __forceinline__ uint32_t sw_off(int row, int gran) {
    return (uint32_t)(row * 64 + ((gran ^ ((row >> 1) & 3)) << 4));
}

__global__ __launch_bounds__(256, 2)
void gemm1_mma(const float* __restrict__ bias, float* __restrict__ h)
{
    extern __shared__ __align__(1024) char smem[];
    const uint32_t sb = smem_u32(smem);
    const int tid = threadIdx.x;
    const int wid = tid >> 5;
    const int lane = tid & 31;
    const int m0 = blockIdx.x * BM;
    const int n0 = blockIdx.y * BN;

    const int warp_m = wid >> 2;
    const int warp_n = wid & 3;

    float acc[4][4][4];
#pragma unroll
    for (int i = 0; i < 4; i++)
#pragma unroll
        for (int j = 0; j < 4; j++)
#pragma unroll
            for (int q = 0; q < 4; q++) acc[i][j][q] = 0.0f;

    const int ar0 = (tid + 0)   >> 2, ag0 = (tid + 0)   & 3;
    const int ar1 = (tid + 256) >> 2, ag1 = (tid + 256) & 3;

    auto issue = [&](int c, int s) {
        const uint32_t abase = sb + s * STAGE_BYTES;
        const uint32_t bbase = abase + BM * BK * 2;
        const __nv_bfloat16* ax = g_xs + (size_t)m0 * KTOT + c * BK;
        const __nv_bfloat16* bx = g_ws + (size_t)n0 * KTOT + c * BK;
        cp16(abase + sw_off(ar0, ag0), ax + (size_t)ar0 * KTOT + ag0 * 8);
        cp16(abase + sw_off(ar1, ag1), ax + (size_t)ar1 * KTOT + ag1 * 8);
        cp16(bbase + sw_off(ar0, ag0), bx + (size_t)ar0 * KTOT + ag0 * 8);
        cp16(bbase + sw_off(ar1, ag1), bx + (size_t)ar1 * KTOT + ag1 * 8);
    };

    issue(0, 0); cp_commit();
    issue(1, 1); cp_commit();
    issue(2, 2); cp_commit();

    const int a_row_in = warp_m * 64 + (lane & 15);
    const int a_gsel   = (lane >> 4);
    const int b_row_in = warp_n * 32 + (lane & 7) + ((lane >> 4) << 3);
    const int b_gsel   = (lane >> 3) & 1;

    for (int c = 0; c < KITERS; c++) {
        asm volatile("cp.async.wait_group 2;" ::: "memory");
        __syncthreads();

        if (c + 3 < KITERS) issue(c + 3, (c + 3) & (NSTAGES - 1));
        cp_commit();

        const uint32_t abase = sb + (c & (NSTAGES - 1)) * STAGE_BYTES;
        const uint32_t bbase = abase + BM * BK * 2;

#pragma unroll
        for (int ks = 0; ks < 2; ks++) {
            uint32_t af[4][4];
            uint32_t bf[4][2];
#pragma unroll
            for (int ti = 0; ti < 4; ti++) {
                const int r = a_row_in + ti * 16;
                ldsm4(af[ti][0], af[ti][1], af[ti][2], af[ti][3],
                      abase + sw_off(r, ks * 2 + a_gsel));
            }
#pragma unroll
            for (int tjj = 0; tjj < 2; tjj++) {
                const int r = b_row_in + tjj * 16;
                uint32_t r0, r1, r2, r3;
                ldsm4(r0, r1, r2, r3, bbase + sw_off(r, ks * 2 + b_gsel));
                bf[tjj * 2 + 0][0] = r0; bf[tjj * 2 + 0][1] = r1;
                bf[tjj * 2 + 1][0] = r2; bf[tjj * 2 + 1][1] = r3;
            }
#pragma unroll
            for (int ti = 0; ti < 4; ti++)
#pragma unroll
                for (int tj = 0; tj < 4; tj++)
                    mma16816(acc[ti][tj], af[ti], bf[tj]);
        }
        __syncthreads();
    }

    __syncthreads();
    float* esm = (float*)smem + wid * (64 * 32);
#pragma unroll
    for (int ti = 0; ti < 4; ti++)
#pragma unroll
        for (int tj = 0; tj < 4; tj++) {
            const int r = ti * 16 + (lane >> 2);
            const int cc = tj * 8 + (lane & 3) * 2;
            esm[r * 32 + cc]            = acc[ti][tj][0];
            esm[r * 32 + cc + 1]        = acc[ti][tj][1];
            esm[(r + 8) * 32 + cc]      = acc[ti][tj][2];
            esm[(r + 8) * 32 + cc + 1]  = acc[ti][tj][3];
        }
    __syncwarp();
    {
        const int col = n0 + warp_n * 32 + lane;
        const float bl = bias[col];
        float* hb = h + (size_t)(m0 + warp_m * 64) * HID_DIM + col;
#pragma unroll 4
        for (int r = 0; r < 64; r++) {
            float v = esm[r * 32 + lane] + bl;
            hb[(size_t)r * HID_DIM] = v > 0.0f ? v : 0.0f;
        }
    }
}

// ---------------------------------------------------------------------------
// transpose dec_w
// ---------------------------------------------------------------------------
__global__ void transpose_dec(const float* __restrict__ dec_w)
{
    __shared__ float tile[32][33];
    const int j0 = blockIdx.x * 32;
    const int o0 = blockIdx.y * 32;
    const int tx = threadIdx.x;
    const int ty = threadIdx.y;
#pragma unroll
    for (int i = 0; i < 4; i++)
        tile[ty + i * 8][tx] = dec_w[(size_t)(o0 + ty + i * 8) * HID_DIM + (j0 + tx)];
    __syncthreads();
#pragma unroll
    for (int i = 0; i < 4; i++)
        g_dec_wT[(size_t)(j0 + ty + i * 8) * OUT_DIM + (o0 + tx)] = tile[tx][ty + i * 8];
}

// ---------------------------------------------------------------------------
// Kernel 3 (redesigned): 1-pass 2048-bin histogram select + exact band +
// compaction + split sparse decode. 512 threads per row.
// ---------------------------------------------------------------------------
__global__ __launch_bounds__(NT)
void topk_apply_gemm2(const float* __restrict__ x,
                      const float* __restrict__ enc_w,
                      const float* __restrict__ enc_b,
                      const float* __restrict__ dec_b,
                      float* __restrict__ out,
                      float* __restrict__ hidden)
{
    extern __shared__ float row[];            // HID_DIM floats
    __shared__ unsigned hist[2048];
    __shared__ int tsum[NT];
    __shared__ int suf[NT];
    __shared__ int cand_idx[CAND_CAP];
    __shared__ float cand_val[CAND_CAP];
    __shared__ unsigned bitmap[HID_DIM / 32];
    __shared__ int list_j[LIST_CAP];
    __shared__ float list_v[LIST_CAP];
    __shared__ float xrow[IN_DIM];
    __shared__ float part[NT];
    __shared__ int band_idx[BAND_CAP];
    __shared__ float band_ex[BAND_CAP];
    __shared__ int wsum[16];
    __shared__ int s_pos, s_ccnt, s_bin, s_hi, s_tbits, s_bandcnt, s_chi, s_total;

    const int tid = threadIdx.x;
    const int lane = tid & 31;
    const int warp = tid >> 5;
    const int brow = blockIdx.x;
    float* hrow = hidden + (size_t)brow * HID_DIM;

    for (int i = tid; i < 2048; i += NT) hist[i] = 0u;
    if (tid < IN_DIM) xrow[tid] = x[(size_t)brow * IN_DIM + tid];
    if (tid == 0) { s_pos = 0; s_ccnt = 0; s_bin = -1; s_hi = 0; s_tbits = 0;
                    s_bandcnt = 0; s_chi = 0; }
    __syncthreads();

    // ---- Phase 1: stage row + histogram of positive values (bins = u>>20) ----
    {
        int my_pos = 0;
        const float4* src = (const float4*)hrow;
        float4* dst = (float4*)row;
        for (int i = tid; i < HID_DIM / 4; i += NT) {
            const float4 v = src[i];
            dst[i] = v;
            if (v.x > 0.0f) { my_pos++; atomicAdd(&hist[__float_as_uint(v.x) >> 20], 1u); }
            if (v.y > 0.0f) { my_pos++; atomicAdd(&hist[__float_as_uint(v.y) >> 20], 1u); }
            if (v.z > 0.0f) { my_pos++; atomicAdd(&hist[__float_as_uint(v.z) >> 20], 1u); }
            if (v.w > 0.0f) { my_pos++; atomicAdd(&hist[__float_as_uint(v.w) >> 20], 1u); }
        }
#pragma unroll
        for (int o = 16; o; o >>= 1) my_pos += __shfl_xor_sync(0xffffffffu, my_pos, o);
        if (lane == 0) atomicAdd(&s_pos, my_pos);
    }
    __syncthreads();

    const bool dense_path = (s_pos < K_SEL);
    float t = 0.0f;

    if (!dense_path) {
        // ---- Phase 2: parallel suffix scan over 2048 bins (4 per thread) ----
        const int b4 = tid * 4;
        const int ts = (int)(hist[b4] + hist[b4 + 1] + hist[b4 + 2] + hist[b4 + 3]);
        tsum[tid] = ts;
        suf[tid] = ts;
        __syncthreads();
        for (int off = 1; off < NT; off <<= 1) {
            const int add = (tid + off < NT) ? suf[tid + off] : 0;
            __syncthreads();
            suf[tid] += add;
            __syncthreads();
        }
        {
            int running = (tid < NT - 1) ? suf[tid + 1] : 0;   // count above my group
            for (int bb = b4 + 3; bb >= b4; bb--) {
                const int c = (int)hist[bb];
                if (running < K_SEL && running + c >= K_SEL) { s_bin = bb; s_hi = running; }
                running += c;
            }
        }
        __syncthreads();
        const int b = s_bin;

        if (b > 0) {
            // ---- Phase 3: collect threshold-bin candidates, rank exactly ----
            for (int i = tid; i < HID_DIM; i += NT) {
                const float v = row[i];
                if (v > 0.0f && (int)(__float_as_uint(v) >> 20) == b) {
                    const int p = atomicAdd(&s_ccnt, 1);
                    if (p < CAND_CAP) { cand_idx[p] = i; cand_val[p] = v; }
                }
            }
            __syncthreads();
            const int C = (s_ccnt < CAND_CAP) ? s_ccnt : CAND_CAP;
            const int k_rem = K_SEL - s_hi;
            for (int c = tid; c < C; c += NT) {
                const float mine = cand_val[c];
                int gt = 0, eq = 0;
                for (int j = 0; j < C; j++) {
                    const float o = cand_val[j];
                    gt += (o > mine); eq += (o == mine);
                }
                if (gt < k_rem && gt + eq >= k_rem) s_tbits = __float_as_int(mine);
            }
            __syncthreads();
            t = __int_as_float(s_tbits);
        } else {
            t = __int_as_float(1);   // degenerate (denormal threshold): keep all positives
        }
    }

    const float eps = 3e-3f;
    const bool band_path = (!dense_path) && (t > eps);

    if (band_path) {
        // ---- Phase 4: exact boundary band ----
        int my_hi = 0;
        for (int w = warp; w < HID_DIM / 32; w += 16) {
            const int i = w * 32 + lane;
            const float v = row[i];
            const bool hi_keep = v > t + eps;
            const unsigned bits = __ballot_sync(0xffffffffu, hi_keep);
            if (lane == 0) bitmap[w] = bits;
            my_hi += hi_keep;
            if ((!hi_keep) && (v >= t - eps)) {
                const int p = atomicAdd(&s_bandcnt, 1);
                if (p < BAND_CAP) band_idx[p] = i;
            }
        }
#pragma unroll
        for (int o = 16; o; o >>= 1) my_hi += __shfl_xor_sync(0xffffffffu, my_hi, o);
        if (lane == 0) atomicAdd(&s_chi, my_hi);
        __syncthreads();

        const int bc = (s_bandcnt < BAND_CAP) ? s_bandcnt : BAND_CAP;
        const int k_remb = K_SEL - s_chi;
        if (tid < bc) {
            const int j = band_idx[tid];
            const float4* wj = (const float4*)(enc_w + (size_t)j * IN_DIM);
            float acc = 0.0f;
#pragma unroll 8
            for (int k4 = 0; k4 < IN_DIM / 4; k4++) {
                const float4 wv = __ldg(&wj[k4]);
                acc = fmaf(xrow[k4 * 4 + 0], wv.x, acc);
                acc = fmaf(xrow[k4 * 4 + 1], wv.y, acc);
                acc = fmaf(xrow[k4 * 4 + 2], wv.z, acc);
                acc = fmaf(xrow[k4 * 4 + 3], wv.w, acc);
            }
            acc += enc_b[j];
            band_ex[tid] = acc > 0.0f ? acc : 0.0f;
        }
        __syncthreads();
        if (tid < bc) {
            const float mine = band_ex[tid];
            int gt = 0;
            for (int j2 = 0; j2 < bc; j2++) gt += (band_ex[j2] > mine);
            const int i = band_idx[tid];
            if (gt < k_remb) {
                row[i] = band_ex[tid];
                atomicOr(&bitmap[i >> 5], 1u << (i & 31));
            }
        }
        __syncthreads();
    }

    // ---- Phase 5: deterministic compaction (warp-shuffle scan) ----
    int cnt = 0;
    if (band_path) {
        for (int i = tid; i < HID_DIM; i += NT)
            cnt += (int)((bitmap[i >> 5] >> (i & 31)) & 1u);
    } else if (!dense_path) {
        for (int i = tid; i < HID_DIM; i += NT)
            cnt += (row[i] >= t);
    }
    int incl = cnt;
#pragma unroll
    for (int o = 1; o < 32; o <<= 1) {
        const int n = __shfl_up_sync(0xffffffffu, incl, o);
        if (lane >= o) incl += n;
    }
    if (lane == 31) wsum[warp] = incl;
    __syncthreads();
    if (warp == 0) {
        const int v = (lane < 16) ? wsum[lane] : 0;
        int s = v;
#pragma unroll
        for (int o = 1; o < 16; o <<= 1) {
            const int n = __shfl_up_sync(0xffffffffu, s, o);
            if (lane >= o) s += n;
        }
        if (lane < 16) wsum[lane] = s - v;
        if (lane == 15) s_total = s;
    }
    __syncthreads();
    int base = wsum[warp] + (incl - cnt);

    if (band_path) {
        for (int i = tid; i < HID_DIM; i += NT) {
            if ((bitmap[i >> 5] >> (i & 31)) & 1u) {
                if (base < LIST_CAP) { list_j[base] = i; list_v[base] = row[i]; }
                base++;
            } else {
                row[i] = 0.0f;
            }
        }
    } else if (!dense_path) {
        for (int i = tid; i < HID_DIM; i += NT) {
            const float v = row[i];
            if (v >= t) {
                if (base < LIST_CAP) { list_j[base] = i; list_v[base] = v; }
                base++;
            } else {
                row[i] = 0.0f;
            }
        }
    }
    __syncthreads();

    // ---- write hidden_post back ----
    {
        const float4* src = (const float4*)row;
        float4* dst = (float4*)hrow;
        for (int i = tid; i < HID_DIM / 4; i += NT) dst[i] = src[i];
    }

    // ---- Phase 6: sparse decode GEMM, split over two half-lists ----
    const int col = tid & 255;
    const int halfid = tid >> 8;
    float acc = 0.0f;
    if (!dense_path) {
        const int nsel = (s_total < LIST_CAP) ? s_total : LIST_CAP;
        const int h1 = nsel >> 1;
        const int s0 = halfid ? h1 : 0;
        const int s1 = halfid ? nsel : h1;
        int s = s0;
        for (; s + 4 <= s1; s += 4) {
            acc = fmaf(list_v[s + 0], g_dec_wT[(size_t)list_j[s + 0] * OUT_DIM + col], acc);
            acc = fmaf(list_v[s + 1], g_dec_wT[(size_t)list_j[s + 1] * OUT_DIM + col], acc);
            acc = fmaf(list_v[s + 2], g_dec_wT[(size_t)list_j[s + 2] * OUT_DIM + col], acc);
            acc = fmaf(list_v[s + 3], g_dec_wT[(size_t)list_j[s + 3] * OUT_DIM + col], acc);
        }
        for (; s < s1; s++)
            acc = fmaf(list_v[s], g_dec_wT[(size_t)list_j[s] * OUT_DIM + col], acc);
    } else {
        const int j0 = halfid * (HID_DIM / 2);
        for (int j = j0; j < j0 + HID_DIM / 2; j++)
            acc = fmaf(row[j], g_dec_wT[(size_t)j * OUT_DIM + col], acc);
    }
    part[tid] = acc;
    __syncthreads();
    if (tid < OUT_DIM)
        out[(size_t)brow * OUT_DIM + tid] = dec_b[tid] + part[tid] + part[tid + 256];
}

// ---------------------------------------------------------------------------
// Launch
// ---------------------------------------------------------------------------
extern "C" void kernel_launch(void* const* d_in, const int* in_sizes, int n_in,
                              void* d_out, int out_size)
{
    const float* x     = (const float*)d_in[0];
    const float* enc_w = (const float*)d_in[1];
    const float* enc_b = (const float*)d_in[2];
    const float* dec_w = (const float*)d_in[3];
    const float* dec_b = (const float*)d_in[4];

    float* out    = (float*)d_out;
    float* hidden = (float*)d_out + (size_t)BATCH * OUT_DIM;

    cudaFuncSetAttribute(topk_apply_gemm2,
                         cudaFuncAttributeMaxDynamicSharedMemorySize,
                         HID_DIM * sizeof(float));
    cudaFuncSetAttribute(gemm1_mma,
                         cudaFuncAttributeMaxDynamicSharedMemorySize,
                         GEMM_SMEM);

    {
        dim3 grid(HID_DIM / 32, OUT_DIM / 32);
        dim3 block(32, 8);
        transpose_dec<<<grid, block>>>(dec_w);
    }
    split_x<<<(BATCH * IN_DIM) / 256, 256>>>(x);
    split_w<<<((size_t)HID_DIM * IN_DIM) / 256, 256>>>(enc_w);

    {
        dim3 grid(BATCH / BM, HID_DIM / BN);
        gemm1_mma<<<grid, 256, GEMM_SMEM>>>(enc_b, hidden);
    }
    topk_apply_gemm2<<<BATCH, NT, HID_DIM * sizeof(float)>>>(
        x, enc_w, enc_b, dec_b, out, hidden);
}

// round 8
// speedup vs baseline: 1.6514x; 1.0135x over previous
#include <cuda_runtime.h>
#include <cuda_bf16.h>
#include <cstdint>

#define BATCH   8192
#define IN_DIM  256
#define HID_DIM 16384
#define OUT_DIM 256
#define K_SEL   256
#define LIST_CAP 320
#define BAND_CAP 64
#define CAND_CAP 768
#define NT3      256

// bf16x2 split GEMM (3 terms): K expanded 3x (hi*hi, hi*mid, mid*hi)
#define KTOT  768

// HMMA tile config
#define BM 128
#define BN 128
#define BK 32
#define NSTAGES 4
#define KITERS (KTOT / BK)
#define STAGE_BYTES (2 * BM * BK * 2)
#define GEMM_SMEM (NSTAGES * STAGE_BYTES)

typedef unsigned long long u64;

__device__ float         g_dec_wT[(size_t)HID_DIM * OUT_DIM];
__device__ __nv_bfloat16 g_xs[(size_t)BATCH  * KTOT];
__device__ __nv_bfloat16 g_ws[(size_t)HID_DIM * KTOT];
__device__ int           g_nsel[BATCH];
__device__ int           g_lj[(size_t)BATCH * LIST_CAP];
__device__ float         g_lv[(size_t)BATCH * LIST_CAP];

// ---------------------------------------------------------------------------
// PTX helpers (sm_80-level only; ptxas targets sm_103 with no 'a' features)
// ---------------------------------------------------------------------------
__device__ __forceinline__ uint32_t smem_u32(const void* p) {
    uint32_t a;
    asm("{ .reg .u64 t; cvta.to.shared.u64 t, %1; cvt.u32.u64 %0, t; }" : "=r"(a) : "l"(p));
    return a;
}
__device__ __forceinline__ void cp16(uint32_t dst, const void* src) {
    asm volatile("cp.async.cg.shared.global [%0], [%1], 16;" :: "r"(dst), "l"(src));
}
__device__ __forceinline__ void cp_commit() {
    asm volatile("cp.async.commit_group;" ::: "memory");
}
__device__ __forceinline__ void ldsm4(uint32_t& r0, uint32_t& r1, uint32_t& r2, uint32_t& r3,
                                      uint32_t addr) {
    asm volatile("ldmatrix.sync.aligned.m8n8.x4.shared.b16 {%0,%1,%2,%3}, [%4];"
                 : "=r"(r0), "=r"(r1), "=r"(r2), "=r"(r3) : "r"(addr));
}
__device__ __forceinline__ void mma16816(float* c, const uint32_t* a, const uint32_t* b) {
    asm volatile(
        "mma.sync.aligned.m16n8k16.row.col.f32.bf16.bf16.f32 "
        "{%0,%1,%2,%3}, {%4,%5,%6,%7}, {%8,%9}, {%0,%1,%2,%3};"
        : "+f"(c[0]), "+f"(c[1]), "+f"(c[2]), "+f"(c[3])
        : "r"(a[0]), "r"(a[1]), "r"(a[2]), "r"(a[3]), "r"(b[0]), "r"(b[1]));
}

// ---------------------------------------------------------------------------
// split fp32 -> 2x bf16 along expanded K (3-term product)
// ---------------------------------------------------------------------------
__global__ void split_x(const float* __restrict__ x)
{
    const int i = blockIdx.x * 256 + threadIdx.x;
    const int m = i >> 8, k = i & 255;
    const float v = x[i];
    const __nv_bfloat16 hi = __float2bfloat16(v);
    const float r1 = v - __bfloat162float(hi);
    const __nv_bfloat16 mid = __float2bfloat16(r1);
    __nv_bfloat16* dst = g_xs + (size_t)m * KTOT + k;
    dst[0] = hi; dst[256] = hi; dst[512] = mid;
}
__global__ void split_w(const float* __restrict__ w)
{
    const int i = blockIdx.x * 256 + threadIdx.x;
    const int n = i >> 8, k = i & 255;
    const float v = w[i];
    const __nv_bfloat16 hi = __float2bfloat16(v);
    const float r1 = v - __bfloat162float(hi);
    const __nv_bfloat16 mid = __float2bfloat16(r1);
    __nv_bfloat16* dst = g_ws + (size_t)n * KTOT + k;
    dst[0] = hi; dst[256] = mid; dst[512] = hi;
}

// ---------------------------------------------------------------------------
// HMMA bf16 GEMM:  h = relu(A' B'^T + bias)  (unchanged)
// ---------------------------------------------------------------------------
__device__ __forceinline__ uint32_t sw_off(int row, int gran) {
    return (uint32_t)(row * 64 + ((gran ^ ((row >> 1) & 3)) << 4));
}

__global__ __launch_bounds__(256, 2)
void gemm1_mma(const float* __restrict__ bias, float* __restrict__ h)
{
    extern __shared__ __align__(1024) char smem[];
    const uint32_t sb = smem_u32(smem);
    const int tid = threadIdx.x;
    const int wid = tid >> 5;
    const int lane = tid & 31;
    const int m0 = blockIdx.x * BM;
    const int n0 = blockIdx.y * BN;

    const int warp_m = wid >> 2;
    const int warp_n = wid & 3;

    float acc[4][4][4];
#pragma unroll
    for (int i = 0; i < 4; i++)
#pragma unroll
        for (int j = 0; j < 4; j++)
#pragma unroll
            for (int q = 0; q < 4; q++) acc[i][j][q] = 0.0f;

    const int ar0 = (tid + 0)   >> 2, ag0 = (tid + 0)   & 3;
    const int ar1 = (tid + 256) >> 2, ag1 = (tid + 256) & 3;

    auto issue = [&](int c, int s) {
        const uint32_t abase = sb + s * STAGE_BYTES;
        const uint32_t bbase = abase + BM * BK * 2;
        const __nv_bfloat16* ax = g_xs + (size_t)m0 * KTOT + c * BK;
        const __nv_bfloat16* bx = g_ws + (size_t)n0 * KTOT + c * BK;
        cp16(abase + sw_off(ar0, ag0), ax + (size_t)ar0 * KTOT + ag0 * 8);
        cp16(abase + sw_off(ar1, ag1), ax + (size_t)ar1 * KTOT + ag1 * 8);
        cp16(bbase + sw_off(ar0, ag0), bx + (size_t)ar0 * KTOT + ag0 * 8);
        cp16(bbase + sw_off(ar1, ag1), bx + (size_t)ar1 * KTOT + ag1 * 8);
    };

    issue(0, 0); cp_commit();
    issue(1, 1); cp_commit();
    issue(2, 2); cp_commit();

    const int a_row_in = warp_m * 64 + (lane & 15);
    const int a_gsel   = (lane >> 4);
    const int b_row_in = warp_n * 32 + (lane & 7) + ((lane >> 4) << 3);
    const int b_gsel   = (lane >> 3) & 1;

    for (int c = 0; c < KITERS; c++) {
        asm volatile("cp.async.wait_group 2;" ::: "memory");
        __syncthreads();

        if (c + 3 < KITERS) issue(c + 3, (c + 3) & (NSTAGES - 1));
        cp_commit();

        const uint32_t abase = sb + (c & (NSTAGES - 1)) * STAGE_BYTES;
        const uint32_t bbase = abase + BM * BK * 2;

#pragma unroll
        for (int ks = 0; ks < 2; ks++) {
            uint32_t af[4][4];
            uint32_t bf[4][2];
#pragma unroll
            for (int ti = 0; ti < 4; ti++) {
                const int r = a_row_in + ti * 16;
                ldsm4(af[ti][0], af[ti][1], af[ti][2], af[ti][3],
                      abase + sw_off(r, ks * 2 + a_gsel));
            }
#pragma unroll
            for (int tjj = 0; tjj < 2; tjj++) {
                const int r = b_row_in + tjj * 16;
                uint32_t r0, r1, r2, r3;
                ldsm4(r0, r1, r2, r3, bbase + sw_off(r, ks * 2 + b_gsel));
                bf[tjj * 2 + 0][0] = r0; bf[tjj * 2 + 0][1] = r1;
                bf[tjj * 2 + 1][0] = r2; bf[tjj * 2 + 1][1] = r3;
            }
#pragma unroll
            for (int ti = 0; ti < 4; ti++)
#pragma unroll
                for (int tj = 0; tj < 4; tj++)
                    mma16816(acc[ti][tj], af[ti], bf[tj]);
        }
        __syncthreads();
    }

    __syncthreads();
    float* esm = (float*)smem + wid * (64 * 32);
#pragma unroll
    for (int ti = 0; ti < 4; ti++)
#pragma unroll
        for (int tj = 0; tj < 4; tj++) {
            const int r = ti * 16 + (lane >> 2);
            const int cc = tj * 8 + (lane & 3) * 2;
            esm[r * 32 + cc]            = acc[ti][tj][0];
            esm[r * 32 + cc + 1]        = acc[ti][tj][1];
            esm[(r + 8) * 32 + cc]      = acc[ti][tj][2];
            esm[(r + 8) * 32 + cc + 1]  = acc[ti][tj][3];
        }
    __syncwarp();
    {
        const int col = n0 + warp_n * 32 + lane;
        const float bl = bias[col];
        float* hb = h + (size_t)(m0 + warp_m * 64) * HID_DIM + col;
#pragma unroll 4
        for (int r = 0; r < 64; r++) {
            float v = esm[r * 32 + lane] + bl;
            hb[(size_t)r * HID_DIM] = v > 0.0f ? v : 0.0f;
        }
    }
}

// ---------------------------------------------------------------------------
// transpose dec_w
// ---------------------------------------------------------------------------
__global__ void transpose_dec(const float* __restrict__ dec_w)
{
    __shared__ float tile[32][33];
    const int j0 = blockIdx.x * 32;
    const int o0 = blockIdx.y * 32;
    const int tx = threadIdx.x;
    const int ty = threadIdx.y;
#pragma unroll
    for (int i = 0; i < 4; i++)
        tile[ty + i * 8][tx] = dec_w[(size_t)(o0 + ty + i * 8) * HID_DIM + (j0 + tx)];
    __syncthreads();
#pragma unroll
    for (int i = 0; i < 4; i++)
        g_dec_wT[(size_t)(j0 + ty + i * 8) * OUT_DIM + (o0 + tx)] = tile[tx][ty + i * 8];
}

// ---------------------------------------------------------------------------
// Kernel 3a: selection. Pass A histograms from DRAM; Pass B re-reads (L2-hot),
// writes hidden_post in place, collects candidates; exact band; compact list.
// ---------------------------------------------------------------------------
__global__ __launch_bounds__(NT3)
void topk_select(const float* __restrict__ x,
                 const float* __restrict__ enc_w,
                 const float* __restrict__ enc_b,
                 float* __restrict__ hidden)
{
    __shared__ unsigned hist[2048];
    __shared__ int scanbuf[NT3];
    __shared__ int cand_idx[CAND_CAP];
    __shared__ float cand_val[CAND_CAP];
    __shared__ float cand_out[CAND_CAP];
    __shared__ unsigned char cand_keep[CAND_CAP];
    __shared__ float xrow[IN_DIM];
    __shared__ int band_c[BAND_CAP];
    __shared__ float band_ex[BAND_CAP];
    __shared__ int wsum[8];
    __shared__ int s_pos, s_ccnt, s_bin, s_hidef, s_tbits, s_def, s_hi2, s_bandcnt, s_keepcnt;

    const int tid = threadIdx.x;
    const int lane = tid & 31, warp = tid >> 5;
    const int brow = blockIdx.x;
    float* hrow = hidden + (size_t)brow * HID_DIM;
    float4* hv = (float4*)hrow;

#pragma unroll
    for (int i = tid; i < 2048; i += NT3) hist[i] = 0u;
    xrow[tid] = x[(size_t)brow * IN_DIM + tid];
    if (tid == 0) { s_pos = 0; s_ccnt = 0; s_bin = -1; s_hidef = 0; s_tbits = 0;
                    s_hi2 = 0; s_bandcnt = 0; s_keepcnt = 0; }
    __syncthreads();

    // ---- Pass A: histogram of positive values (bins = u>>20) ----
    {
        int my_pos = 0;
        for (int i = tid; i < HID_DIM / 4; i += NT3) {
            const float4 v = hv[i];
            if (v.x > 0.0f) { my_pos++; atomicAdd(&hist[__float_as_uint(v.x) >> 20], 1u); }
            if (v.y > 0.0f) { my_pos++; atomicAdd(&hist[__float_as_uint(v.y) >> 20], 1u); }
            if (v.z > 0.0f) { my_pos++; atomicAdd(&hist[__float_as_uint(v.z) >> 20], 1u); }
            if (v.w > 0.0f) { my_pos++; atomicAdd(&hist[__float_as_uint(v.w) >> 20], 1u); }
        }
#pragma unroll
        for (int o = 16; o; o >>= 1) my_pos += __shfl_xor_sync(0xffffffffu, my_pos, o);
        if (lane == 0) atomicAdd(&s_pos, my_pos);
    }
    __syncthreads();

    if (s_pos < K_SEL) {                 // dense: hidden_post == h_relu already
        if (tid == 0) g_nsel[brow] = -1;
        return;
    }

    // ---- suffix scan over 2048 bins, find threshold bin b ----
    const int b8 = tid * 8;
    {
        int ts = 0;
#pragma unroll
        for (int q = 0; q < 8; q++) ts += (int)hist[b8 + q];
        scanbuf[tid] = ts;
        __syncthreads();
        for (int off = 1; off < NT3; off <<= 1) {
            const int add = (tid + off < NT3) ? scanbuf[tid + off] : 0;
            __syncthreads();
            scanbuf[tid] += add;
            __syncthreads();
        }
        int running = (tid < NT3 - 1) ? scanbuf[tid + 1] : 0;
        for (int bb = b8 + 7; bb >= b8; bb--) {
            const int c = (int)hist[bb];
            if (running < K_SEL && running + c >= K_SEL) s_bin = bb;
            running += c;
        }
    }
    __syncthreads();
    const int b = s_bin;
    if (b <= 8) {                        // degenerate subnormal threshold
        if (tid == 0) g_nsel[brow] = -1;
        return;
    }
    // hi_def = count in bins >= b+2
    {
        int part = 0;
#pragma unroll
        for (int q = 0; q < 8; q++) { const int bb = b8 + q; if (bb >= b + 2) part += (int)hist[bb]; }
#pragma unroll
        for (int o = 16; o; o >>= 1) part += __shfl_xor_sync(0xffffffffu, part, o);
        if (lane == 0) atomicAdd(&s_hidef, part);
    }
    __syncthreads();

    // ---- Pass B: write post (definite/zero) in place, collect candidates ----
    int cnt = 0;
    for (int i = tid; i < HID_DIM / 4; i += NT3) {
        float4 v = hv[i];
        float4 o;
        {
            const int ub = (int)(__float_as_uint(v.x) >> 20);
            if (v.x > 0.0f && ub >= b + 2) { o.x = v.x; cnt++; }
            else { o.x = 0.0f; if (v.x > 0.0f && ub >= b - 1 && ub <= b + 1) {
                const int p = atomicAdd(&s_ccnt, 1);
                if (p < CAND_CAP) { cand_idx[p] = i * 4 + 0; cand_val[p] = v.x; } } }
        }
        {
            const int ub = (int)(__float_as_uint(v.y) >> 20);
            if (v.y > 0.0f && ub >= b + 2) { o.y = v.y; cnt++; }
            else { o.y = 0.0f; if (v.y > 0.0f && ub >= b - 1 && ub <= b + 1) {
                const int p = atomicAdd(&s_ccnt, 1);
                if (p < CAND_CAP) { cand_idx[p] = i * 4 + 1; cand_val[p] = v.y; } } }
        }
        {
            const int ub = (int)(__float_as_uint(v.z) >> 20);
            if (v.z > 0.0f && ub >= b + 2) { o.z = v.z; cnt++; }
            else { o.z = 0.0f; if (v.z > 0.0f && ub >= b - 1 && ub <= b + 1) {
                const int p = atomicAdd(&s_ccnt, 1);
                if (p < CAND_CAP) { cand_idx[p] = i * 4 + 2; cand_val[p] = v.z; } } }
        }
        {
            const int ub = (int)(__float_as_uint(v.w) >> 20);
            if (v.w > 0.0f && ub >= b + 2) { o.w = v.w; cnt++; }
            else { o.w = 0.0f; if (v.w > 0.0f && ub >= b - 1 && ub <= b + 1) {
                const int p = atomicAdd(&s_ccnt, 1);
                if (p < CAND_CAP) { cand_idx[p] = i * 4 + 3; cand_val[p] = v.w; } } }
        }
        hv[i] = o;
    }
    __syncthreads();

    // ---- scan definite counts -> deterministic list bases ----
    int incl = cnt;
#pragma unroll
    for (int o = 1; o < 32; o <<= 1) {
        const int n = __shfl_up_sync(0xffffffffu, incl, o);
        if (lane >= o) incl += n;
    }
    if (lane == 31) wsum[warp] = incl;
    __syncthreads();
    if (warp == 0 && lane < 8) {
        int v = wsum[lane];
        int s = v;
#pragma unroll
        for (int o = 1; o < 8; o <<= 1) {
            const int n = __shfl_up_sync(0x000000ffu, s, o);
            if (lane >= o) s += n;
        }
        wsum[lane] = s - v;
        if (lane == 7) s_def = s;
    }
    __syncthreads();
    int base = wsum[warp] + (incl - cnt);

    // append definites — SAME float4-strided partition as the counting pass
    // (round-7 bug: this walk was scalar-strided, mismatching `cnt` → corrupt lists)
    for (int i = tid; i < HID_DIM / 4; i += NT3) {
        const float4 v = hv[i];
        if (v.x != 0.0f) {
            if (base < LIST_CAP) { g_lj[(size_t)brow * LIST_CAP + base] = i * 4 + 0;
                                   g_lv[(size_t)brow * LIST_CAP + base] = v.x; }
            base++;
        }
        if (v.y != 0.0f) {
            if (base < LIST_CAP) { g_lj[(size_t)brow * LIST_CAP + base] = i * 4 + 1;
                                   g_lv[(size_t)brow * LIST_CAP + base] = v.y; }
            base++;
        }
        if (v.z != 0.0f) {
            if (base < LIST_CAP) { g_lj[(size_t)brow * LIST_CAP + base] = i * 4 + 2;
                                   g_lv[(size_t)brow * LIST_CAP + base] = v.z; }
            base++;
        }
        if (v.w != 0.0f) {
            if (base < LIST_CAP) { g_lj[(size_t)brow * LIST_CAP + base] = i * 4 + 3;
                                   g_lv[(size_t)brow * LIST_CAP + base] = v.w; }
            base++;
        }
    }

    // ---- exact threshold among candidates ----
    const int C = (s_ccnt < CAND_CAP) ? s_ccnt : CAND_CAP;
    const int k_rem = K_SEL - s_hidef;
    for (int c = tid; c < C; c += NT3) {
        const float mine = cand_val[c];
        int gt = 0, eq = 0;
        for (int j = 0; j < C; j++) {
            const float o = cand_val[j];
            gt += (o > mine); eq += (o == mine);
        }
        if (gt < k_rem && gt + eq >= k_rem) s_tbits = __float_as_int(mine);
    }
    __syncthreads();
    const float t = __int_as_float(s_tbits);
    const float eps = 3e-3f;

    // classify candidates: definite-above-band / band / out
    for (int c = tid; c < C; c += NT3) {
        const float v = cand_val[c];
        if (v > t + eps) { cand_keep[c] = 1; cand_out[c] = v; atomicAdd(&s_hi2, 1); }
        else if (v >= t - eps) {
            cand_keep[c] = 0;
            const int p = atomicAdd(&s_bandcnt, 1);
            if (p < BAND_CAP) band_c[p] = c;
        } else cand_keep[c] = 0;
    }
    __syncthreads();
    const int bc = (s_bandcnt < BAND_CAP) ? s_bandcnt : BAND_CAP;
    const int k_remb = k_rem - s_hi2;
    if (tid < bc) {
        const int j = cand_idx[band_c[tid]];
        const float4* wj = (const float4*)(enc_w + (size_t)j * IN_DIM);
        float acc = 0.0f;
#pragma unroll 8
        for (int k4 = 0; k4 < IN_DIM / 4; k4++) {
            const float4 wv = __ldg(&wj[k4]);
            acc = fmaf(xrow[k4 * 4 + 0], wv.x, acc);
            acc = fmaf(xrow[k4 * 4 + 1], wv.y, acc);
            acc = fmaf(xrow[k4 * 4 + 2], wv.z, acc);
            acc = fmaf(xrow[k4 * 4 + 3], wv.w, acc);
        }
        acc += enc_b[j];
        band_ex[tid] = acc > 0.0f ? acc : 0.0f;
    }
    __syncthreads();
    if (tid < bc) {
        const float mine = band_ex[tid];
        int gt = 0;
        for (int q = 0; q < bc; q++) gt += (band_ex[q] > mine);
        if (gt < k_remb) {
            const int c = band_c[tid];
            cand_keep[c] = 1;
            cand_out[c] = band_ex[tid];
        }
    }
    __syncthreads();

    // append kept candidates in index order; patch hidden
    for (int c = tid; c < C; c += NT3) {
        if (cand_keep[c]) {
            const int myidx = cand_idx[c];
            int pos = 0;
            for (int j = 0; j < C; j++)
                pos += (cand_keep[j] && cand_idx[j] < myidx);
            const int slot = s_def + pos;
            if (slot < LIST_CAP) {
                g_lj[(size_t)brow * LIST_CAP + slot] = myidx;
                g_lv[(size_t)brow * LIST_CAP + slot] = cand_out[c];
            }
            hrow[myidx] = cand_out[c];
            atomicAdd(&s_keepcnt, 1);
        }
    }
    __syncthreads();
    if (tid == 0) {
        int n = s_def + s_keepcnt;
        g_nsel[brow] = (n < LIST_CAP) ? n : LIST_CAP;
    }
}

// ---------------------------------------------------------------------------
// Kernel 3b: sparse decode GEMM from compact lists (L2-bound, high occupancy)
// ---------------------------------------------------------------------------
__global__ __launch_bounds__(256)
void gemm2_sparse(const float* __restrict__ dec_b,
                  const float* __restrict__ hidden,
                  float* __restrict__ out)
{
    __shared__ int lj[LIST_CAP];
    __shared__ float lv[LIST_CAP];
    const int tid = threadIdx.x;
    const int brow = blockIdx.x;
    const int nsel = g_nsel[brow];

    float acc = dec_b[tid];
    if (nsel >= 0) {
        for (int i = tid; i < nsel; i += 256) {
            lj[i] = g_lj[(size_t)brow * LIST_CAP + i];
            lv[i] = g_lv[(size_t)brow * LIST_CAP + i];
        }
        __syncthreads();
        int s = 0;
        for (; s + 4 <= nsel; s += 4) {
            acc = fmaf(lv[s + 0], g_dec_wT[(size_t)lj[s + 0] * OUT_DIM + tid], acc);
            acc = fmaf(lv[s + 1], g_dec_wT[(size_t)lj[s + 1] * OUT_DIM + tid], acc);
            acc = fmaf(lv[s + 2], g_dec_wT[(size_t)lj[s + 2] * OUT_DIM + tid], acc);
            acc = fmaf(lv[s + 3], g_dec_wT[(size_t)lj[s + 3] * OUT_DIM + tid], acc);
        }
        for (; s < nsel; s++)
            acc = fmaf(lv[s], g_dec_wT[(size_t)lj[s] * OUT_DIM + tid], acc);
    } else {
        const float* hrow = hidden + (size_t)brow * HID_DIM;
        for (int j = 0; j < HID_DIM; j++)
            acc = fmaf(__ldg(&hrow[j]), g_dec_wT[(size_t)j * OUT_DIM + tid], acc);
    }
    out[(size_t)brow * OUT_DIM + tid] = acc;
}

// ---------------------------------------------------------------------------
// Launch
// ---------------------------------------------------------------------------
extern "C" void kernel_launch(void* const* d_in, const int* in_sizes, int n_in,
                              void* d_out, int out_size)
{
    const float* x     = (const float*)d_in[0];
    const float* enc_w = (const float*)d_in[1];
    const float* enc_b = (const float*)d_in[2];
    const float* dec_w = (const float*)d_in[3];
    const float* dec_b = (const float*)d_in[4];

    float* out    = (float*)d_out;
    float* hidden = (float*)d_out + (size_t)BATCH * OUT_DIM;

    cudaFuncSetAttribute(gemm1_mma,
                         cudaFuncAttributeMaxDynamicSharedMemorySize,
                         GEMM_SMEM);

    {
        dim3 grid(HID_DIM / 32, OUT_DIM / 32);
        dim3 block(32, 8);
        transpose_dec<<<grid, block>>>(dec_w);
    }
    split_x<<<(BATCH * IN_DIM) / 256, 256>>>(x);
    split_w<<<((size_t)HID_DIM * IN_DIM) / 256, 256>>>(enc_w);

    {
        dim3 grid(BATCH / BM, HID_DIM / BN);
        gemm1_mma<<<grid, 256, GEMM_SMEM>>>(enc_b, hidden);
    }
    topk_select<<<BATCH, NT3>>>(x, enc_w, enc_b, hidden);
    gemm2_sparse<<<BATCH, 256>>>(dec_b, hidden, out);
}